// round 9
// baseline (speedup 1.0000x reference)
#include <cuda_runtime.h>
#include <math.h>

// Problem constants (fixed by setup_inputs)
#define NN 100000
#define EE 1600000
#define HH 4
#define CC 16
#define DD 64
#define FF 128
#define ET_MAX (EE + NN)
#define NODES_PER_BLK 1024
#define MAX_SCAN_BLKS 128

// ---------------- scratch (device globals; no runtime allocation) ----------------
// INVARIANTS at kernel_launch entry (zero-init at load; restored every call):
//   g_deg  all-zero  (scan_lookback re-zeroes after consuming)
//   g_flag all-zero  (scatter8 re-zeroes after scan completes)
// g_csr_src holds BYTE offsets (node*256); 16-entry zero pad for lookahead.
__device__ float g_xl[(size_t)NN * DD];
__device__ float g_xr[(size_t)NN * DD];
__device__ float g_h1[(size_t)NN * DD];
__device__ int   g_deg[NN];
__device__ int   g_off[NN + 1];
__device__ int   g_cur[NN];
__device__ unsigned g_flag[MAX_SCAN_BLKS];
__device__ int   g_csr_src[ET_MAX + 16];

// ---------------- helpers ----------------
__device__ __forceinline__ void ffma2(unsigned long long& acc,
                                      unsigned long long a, unsigned long long b) {
    asm("fma.rn.f32x2 %0, %1, %2, %0;" : "+l"(acc) : "l"(a), "l"(b));
}
__device__ __forceinline__ unsigned long long bcast2(float v) {
    unsigned long long r;
    asm("mov.b64 %0, {%1, %1};" : "=l"(r) : "r"(__float_as_uint(v)));
    return r;
}

// ================= GEMM body: 128 rows x (Wl||Wr 64+64 cols), 8x8 per thread =================
template<int K>
__device__ __forceinline__ void gemm_body(int blk,
                                          const float* __restrict__ X,
                                          const float* __restrict__ Wl,
                                          const float* __restrict__ Wr,
                                          float* __restrict__ xl,
                                          float* __restrict__ xr, int n,
                                          float (*As)[132], float (*Bs)[132]) {
    int tid = threadIdx.x;
    int rg = tid >> 4;
    int cg = tid & 15;
    int row0 = blk * 128;

    unsigned long long cl[8][2], cr[8][2];
#pragma unroll
    for (int i = 0; i < 8; i++) { cl[i][0] = cl[i][1] = cr[i][0] = cr[i][1] = 0ULL; }

    int lr  = tid >> 1;
    int lks = (tid & 1) * 8;
    int bk  = tid >> 4;
    int bc  = (tid & 15) * 8;

    for (int kc = 0; kc < K; kc += 16) {
        {
            int grow = row0 + lr;
            float4 v0 = make_float4(0.f, 0.f, 0.f, 0.f), v1 = v0;
            if (grow < n) {
                const float* g = X + (size_t)grow * K + kc + lks;
                v0 = *(const float4*)g;
                v1 = *(const float4*)(g + 4);
            }
            As[lks + 0][lr] = v0.x; As[lks + 1][lr] = v0.y;
            As[lks + 2][lr] = v0.z; As[lks + 3][lr] = v0.w;
            As[lks + 4][lr] = v1.x; As[lks + 5][lr] = v1.y;
            As[lks + 6][lr] = v1.z; As[lks + 7][lr] = v1.w;
        }
        {
            const float* wsrc = (bc < 64) ? (Wl + (size_t)(kc + bk) * DD + bc)
                                          : (Wr + (size_t)(kc + bk) * DD + (bc - 64));
            *(float4*)&Bs[bk][bc]     = *(const float4*)wsrc;
            *(float4*)&Bs[bk][bc + 4] = *(const float4*)(wsrc + 4);
        }
        __syncthreads();

#pragma unroll
        for (int k = 0; k < 16; k++) {
            float4 a01 = *(const float4*)&As[k][rg * 8];
            float4 a23 = *(const float4*)&As[k][rg * 8 + 4];
            ulonglong2 bl = *(const ulonglong2*)&Bs[k][cg * 4];
            ulonglong2 br = *(const ulonglong2*)&Bs[k][cg * 4 + 64];
            unsigned long long ab[8];
            ab[0] = bcast2(a01.x); ab[1] = bcast2(a01.y);
            ab[2] = bcast2(a01.z); ab[3] = bcast2(a01.w);
            ab[4] = bcast2(a23.x); ab[5] = bcast2(a23.y);
            ab[6] = bcast2(a23.z); ab[7] = bcast2(a23.w);
#pragma unroll
            for (int i = 0; i < 8; i++) {
                ffma2(cl[i][0], ab[i], bl.x); ffma2(cl[i][1], ab[i], bl.y);
                ffma2(cr[i][0], ab[i], br.x); ffma2(cr[i][1], ab[i], br.y);
            }
        }
        __syncthreads();
    }

#pragma unroll
    for (int i = 0; i < 8; i++) {
        int row = row0 + rg * 8 + i;
        if (row < n) {
            *(ulonglong2*)(xl + (size_t)row * DD + cg * 4) = make_ulonglong2(cl[i][0], cl[i][1]);
            *(ulonglong2*)(xr + (size_t)row * DD + cg * 4) = make_ulonglong2(cr[i][0], cr[i][1]);
        }
    }
}

// ---------------- hist body: 8 edges per thread ----------------
__device__ __forceinline__ void hist_body(int blk, const int* __restrict__ dst, int E) {
    int i = (blk * 256 + threadIdx.x) * 8;
    if (i + 7 < E) {
        int4 a = *(const int4*)(dst + i);
        int4 b = *(const int4*)(dst + i + 4);
        atomicAdd(&g_deg[a.x], 1); atomicAdd(&g_deg[a.y], 1);
        atomicAdd(&g_deg[a.z], 1); atomicAdd(&g_deg[a.w], 1);
        atomicAdd(&g_deg[b.x], 1); atomicAdd(&g_deg[b.y], 1);
        atomicAdd(&g_deg[b.z], 1); atomicAdd(&g_deg[b.w], 1);
    } else {
        for (int j = 0; j < 8; j++)
            if (i + j < E) atomicAdd(&g_deg[__ldg(dst + i + j)], 1);
    }
}

// ================= fat kernel 1: gemm1 (even blocks) + hist (odd blocks) =================
__global__ __launch_bounds__(256, 2)
void fat_gemm1_hist(const float* __restrict__ X,
                    const float* __restrict__ Wl,
                    const float* __restrict__ Wr,
                    float* __restrict__ xl, float* __restrict__ xr, int n,
                    const int* __restrict__ dst, int E, int gGemm, int gHist) {
    __shared__ float As[16][132];
    __shared__ float Bs[16][132];
    int bid = blockIdx.x;
    int g = bid >> 1;
    if ((bid & 1) == 0) {
        if (g < gGemm) gemm_body<FF>(g, X, Wl, Wr, xl, xr, n, As, Bs);
    } else {
        if (g < gHist) hist_body(g, dst, E);
    }
}

// ================= standalone GEMM (layer 2) =================
template<int K>
__global__ __launch_bounds__(256, 2)
void gemm_tiled(const float* __restrict__ X,
                const float* __restrict__ Wl,
                const float* __restrict__ Wr,
                float* __restrict__ xl, float* __restrict__ xr, int n) {
    __shared__ float As[16][132];
    __shared__ float Bs[16][132];
    gemm_body<K>(blockIdx.x, X, Wl, Wr, xl, xr, n, As, Bs);
}

// ================= decoupled-lookback scan (one kernel) =================
__global__ void scan_lookback(int n, int nblk) {
    __shared__ int sh[256];
    __shared__ int s_prefix;
    int t = threadIdx.x, b = blockIdx.x;
    int i0 = b * NODES_PER_BLK + t * 4;

    int d0 = 0, d1 = 0, d2 = 0, d3 = 0;
    if (i0 + 3 < n) {
        int4 d = *(const int4*)(g_deg + i0);
        d0 = d.x + 1; d1 = d.y + 1; d2 = d.z + 1; d3 = d.w + 1;
        *(int4*)(g_deg + i0) = make_int4(0, 0, 0, 0);
    } else {
        if (i0 + 0 < n) { d0 = g_deg[i0 + 0] + 1; g_deg[i0 + 0] = 0; }
        if (i0 + 1 < n) { d1 = g_deg[i0 + 1] + 1; g_deg[i0 + 1] = 0; }
        if (i0 + 2 < n) { d2 = g_deg[i0 + 2] + 1; g_deg[i0 + 2] = 0; }
        if (i0 + 3 < n) { d3 = g_deg[i0 + 3] + 1; g_deg[i0 + 3] = 0; }
    }
    int tsum = d0 + d1 + d2 + d3;
    sh[t] = tsum; __syncthreads();
    for (int d = 1; d < 256; d <<= 1) {
        int v = (t >= d) ? sh[t - d] : 0;
        __syncthreads();
        sh[t] += v;
        __syncthreads();
    }
    int T = sh[255];

    volatile unsigned* flag = g_flag;
    if (t == 0) {
        if (b == 0) {
            s_prefix = 0;
            flag[0] = (2u << 30) | (unsigned)T;
        } else {
            flag[b] = (1u << 30) | (unsigned)T;
            unsigned run = 0;
            int j = b - 1;
            while (true) {
                unsigned v = flag[j];
                unsigned st = v >> 30;
                if (st == 0) continue;
                run += v & 0x3FFFFFFFu;
                if (st == 2u) break;
                j--;
            }
            s_prefix = (int)run;
            flag[b] = (2u << 30) | (run + (unsigned)T);
        }
    }
    __syncthreads();
    int base = s_prefix + sh[t] - tsum;

    int dd[4] = {d0, d1, d2, d3};
    int o = base;
    for (int j = 0; j < 4; j++) {
        int i = i0 + j;
        if (i < n) {
            g_off[i] = o;
            g_csr_src[o] = i << 8;     // self loop first (BYTE offset: node*256)
            g_cur[i] = o + 1;
        }
        o += dd[j];
    }
    if (b == nblk - 1 && t == 255) g_off[n] = s_prefix + T;
}

// ================= scatter (stores BYTE offsets; restores g_flag) =================
__global__ void scatter8(const int* __restrict__ src,
                         const int* __restrict__ dst, int E) {
    if (blockIdx.x == 0 && threadIdx.x < MAX_SCAN_BLKS)
        g_flag[threadIdx.x] = 0;
    int i = (blockIdx.x * blockDim.x + threadIdx.x) * 8;
    if (i + 7 < E) {
        int4 sa = *(const int4*)(src + i);
        int4 da = *(const int4*)(dst + i);
        int4 sb = *(const int4*)(src + i + 4);
        int4 db = *(const int4*)(dst + i + 4);
        int p0 = atomicAdd(&g_cur[da.x], 1);
        int p1 = atomicAdd(&g_cur[da.y], 1);
        int p2 = atomicAdd(&g_cur[da.z], 1);
        int p3 = atomicAdd(&g_cur[da.w], 1);
        int p4 = atomicAdd(&g_cur[db.x], 1);
        int p5 = atomicAdd(&g_cur[db.y], 1);
        int p6 = atomicAdd(&g_cur[db.z], 1);
        int p7 = atomicAdd(&g_cur[db.w], 1);
        g_csr_src[p0] = sa.x << 8; g_csr_src[p1] = sa.y << 8;
        g_csr_src[p2] = sa.z << 8; g_csr_src[p3] = sa.w << 8;
        g_csr_src[p4] = sb.x << 8; g_csr_src[p5] = sb.y << 8;
        g_csr_src[p6] = sb.z << 8; g_csr_src[p7] = sb.w << 8;
    } else {
        for (int j = 0; j < 8; j++)
            if (i + j < E) {
                int s = __ldg(src + i + j), d = __ldg(dst + i + j);
                g_csr_src[atomicAdd(&g_cur[d], 1)] = s << 8;
            }
    }
}

// ================= fused GATv2 attention + aggregate + bias + ReLU =================
// warp per dst node. Lane layout: es = lane>>2 (8 edge slots/step), h = lane&3
// (head). Each lane computes its head's FULL dot product (C=16 dims in
// registers) -> NO shuffles and 1 warp-MUFU per 8 edges. Per-node epilogue
// butterfly (xor 4/8/16) combines the 8 edge slots.
// lrelu(u)*a summed via t = 0.6*(sum a*u) + 0.4*(sum a*|u|); |u| is a free
// FFMA operand modifier.
__global__ void __launch_bounds__(256)
gat_node(const float* __restrict__ xl,
         const float* __restrict__ xr,
         const float* __restrict__ att,
         const float* __restrict__ bias,
         float* __restrict__ out, int n) {
    int w    = (blockIdx.x * blockDim.x + threadIdx.x) >> 5;
    int lane = threadIdx.x & 31;
    if (w >= n) return;
    int es = lane >> 2;      // edge slot 0..7
    int h  = lane & 3;       // head 0..3

    // per-lane base: head offset within a row (h*16 floats = h*64 bytes)
    const char* xlb = (const char*)xl + h * 64;

    const float4* xrh = (const float4*)(xr + (size_t)w * DD + h * CC);
    float4 x0 = xrh[0], x1 = xrh[1], x2 = xrh[2], x3 = xrh[3];
    const float4* ah = (const float4*)(att + h * CC);
    float4 A0 = ah[0], A1 = ah[1], A2 = ah[2], A3 = ah[3];

    int beg = g_off[w], end = g_off[w + 1];
    int rem = end - beg;
    const int* ip = g_csr_src + beg;

    float s = 0.f;
    float4 c0 = make_float4(0.f, 0.f, 0.f, 0.f), c1 = c0, c2 = c0, c3 = c0;

    int off = __ldg(ip + es);
    for (int i = 0; i < rem; i += 8) {
        int noff = __ldg(ip + i + 8 + es);      // prefetch next step's offset
        const char* base = xlb + off;
        float4 v0 = *(const float4*)(base);
        float4 v1 = *(const float4*)(base + 16);
        float4 v2 = *(const float4*)(base + 32);
        float4 v3 = *(const float4*)(base + 48);

        float tl = 0.f, ta = 0.f, u;
        u = v0.x + x0.x; tl = fmaf(A0.x, u, tl); ta = fmaf(A0.x, fabsf(u), ta);
        u = v0.y + x0.y; tl = fmaf(A0.y, u, tl); ta = fmaf(A0.y, fabsf(u), ta);
        u = v0.z + x0.z; tl = fmaf(A0.z, u, tl); ta = fmaf(A0.z, fabsf(u), ta);
        u = v0.w + x0.w; tl = fmaf(A0.w, u, tl); ta = fmaf(A0.w, fabsf(u), ta);
        u = v1.x + x1.x; tl = fmaf(A1.x, u, tl); ta = fmaf(A1.x, fabsf(u), ta);
        u = v1.y + x1.y; tl = fmaf(A1.y, u, tl); ta = fmaf(A1.y, fabsf(u), ta);
        u = v1.z + x1.z; tl = fmaf(A1.z, u, tl); ta = fmaf(A1.z, fabsf(u), ta);
        u = v1.w + x1.w; tl = fmaf(A1.w, u, tl); ta = fmaf(A1.w, fabsf(u), ta);
        u = v2.x + x2.x; tl = fmaf(A2.x, u, tl); ta = fmaf(A2.x, fabsf(u), ta);
        u = v2.y + x2.y; tl = fmaf(A2.y, u, tl); ta = fmaf(A2.y, fabsf(u), ta);
        u = v2.z + x2.z; tl = fmaf(A2.z, u, tl); ta = fmaf(A2.z, fabsf(u), ta);
        u = v2.w + x2.w; tl = fmaf(A2.w, u, tl); ta = fmaf(A2.w, fabsf(u), ta);
        u = v3.x + x3.x; tl = fmaf(A3.x, u, tl); ta = fmaf(A3.x, fabsf(u), ta);
        u = v3.y + x3.y; tl = fmaf(A3.y, u, tl); ta = fmaf(A3.y, fabsf(u), ta);
        u = v3.z + x3.z; tl = fmaf(A3.z, u, tl); ta = fmaf(A3.z, fabsf(u), ta);
        u = v3.w + x3.w; tl = fmaf(A3.w, u, tl); ta = fmaf(A3.w, fabsf(u), ta);

        float t = 0.6f * tl + 0.4f * ta;
        float p = (i + es < rem) ? __expf(t) : 0.f;
        s += p;
        c0.x = fmaf(p, v0.x, c0.x); c0.y = fmaf(p, v0.y, c0.y);
        c0.z = fmaf(p, v0.z, c0.z); c0.w = fmaf(p, v0.w, c0.w);
        c1.x = fmaf(p, v1.x, c1.x); c1.y = fmaf(p, v1.y, c1.y);
        c1.z = fmaf(p, v1.z, c1.z); c1.w = fmaf(p, v1.w, c1.w);
        c2.x = fmaf(p, v2.x, c2.x); c2.y = fmaf(p, v2.y, c2.y);
        c2.z = fmaf(p, v2.z, c2.z); c2.w = fmaf(p, v2.w, c2.w);
        c3.x = fmaf(p, v3.x, c3.x); c3.y = fmaf(p, v3.y, c3.y);
        c3.z = fmaf(p, v3.z, c3.z); c3.w = fmaf(p, v3.w, c3.w);

        off = noff;
    }

    // butterfly over the 8 edge slots (lanes with equal h)
#pragma unroll
    for (int m = 4; m < 32; m <<= 1) {
        s    += __shfl_xor_sync(0xffffffffu, s,    m);
        c0.x += __shfl_xor_sync(0xffffffffu, c0.x, m);
        c0.y += __shfl_xor_sync(0xffffffffu, c0.y, m);
        c0.z += __shfl_xor_sync(0xffffffffu, c0.z, m);
        c0.w += __shfl_xor_sync(0xffffffffu, c0.w, m);
        c1.x += __shfl_xor_sync(0xffffffffu, c1.x, m);
        c1.y += __shfl_xor_sync(0xffffffffu, c1.y, m);
        c1.z += __shfl_xor_sync(0xffffffffu, c1.z, m);
        c1.w += __shfl_xor_sync(0xffffffffu, c1.w, m);
        c2.x += __shfl_xor_sync(0xffffffffu, c2.x, m);
        c2.y += __shfl_xor_sync(0xffffffffu, c2.y, m);
        c2.z += __shfl_xor_sync(0xffffffffu, c2.z, m);
        c2.w += __shfl_xor_sync(0xffffffffu, c2.w, m);
        c3.x += __shfl_xor_sync(0xffffffffu, c3.x, m);
        c3.y += __shfl_xor_sync(0xffffffffu, c3.y, m);
        c3.z += __shfl_xor_sync(0xffffffffu, c3.z, m);
        c3.w += __shfl_xor_sync(0xffffffffu, c3.w, m);
    }

    if (es == 0) {
        const float4* bh = (const float4*)(bias + h * CC);
        float4 b0 = bh[0], b1 = bh[1], b2 = bh[2], b3 = bh[3];
        float inv = __fdividef(1.f, s);
        float4 o0, o1, o2, o3;
        o0.x = fmaxf(fmaf(c0.x, inv, b0.x), 0.f);
        o0.y = fmaxf(fmaf(c0.y, inv, b0.y), 0.f);
        o0.z = fmaxf(fmaf(c0.z, inv, b0.z), 0.f);
        o0.w = fmaxf(fmaf(c0.w, inv, b0.w), 0.f);
        o1.x = fmaxf(fmaf(c1.x, inv, b1.x), 0.f);
        o1.y = fmaxf(fmaf(c1.y, inv, b1.y), 0.f);
        o1.z = fmaxf(fmaf(c1.z, inv, b1.z), 0.f);
        o1.w = fmaxf(fmaf(c1.w, inv, b1.w), 0.f);
        o2.x = fmaxf(fmaf(c2.x, inv, b2.x), 0.f);
        o2.y = fmaxf(fmaf(c2.y, inv, b2.y), 0.f);
        o2.z = fmaxf(fmaf(c2.z, inv, b2.z), 0.f);
        o2.w = fmaxf(fmaf(c2.w, inv, b2.w), 0.f);
        o3.x = fmaxf(fmaf(c3.x, inv, b3.x), 0.f);
        o3.y = fmaxf(fmaf(c3.y, inv, b3.y), 0.f);
        o3.z = fmaxf(fmaf(c3.z, inv, b3.z), 0.f);
        o3.w = fmaxf(fmaf(c3.w, inv, b3.w), 0.f);
        float4* op = (float4*)(out + (size_t)w * DD + h * CC);
        op[0] = o0; op[1] = o1; op[2] = o2; op[3] = o3;
    }
}

// ---------------- launch ----------------
extern "C" void kernel_launch(void* const* d_in, const int* in_sizes, int n_in,
                              void* d_out, int out_size) {
    const float* x    = (const float*)d_in[0];
    const int*   edge = (const int*)  d_in[1];
    const float* W1l  = (const float*)d_in[2];
    const float* W1r  = (const float*)d_in[3];
    const float* att1 = (const float*)d_in[4];
    const float* b1   = (const float*)d_in[5];
    const float* W2l  = (const float*)d_in[6];
    const float* W2r  = (const float*)d_in[7];
    const float* att2 = (const float*)d_in[8];
    const float* b2   = (const float*)d_in[9];

    int E = in_sizes[1] / 2;
    int N = in_sizes[0] / FF;
    const int* srcp = edge;
    const int* dstp = edge + E;
    float* out = (float*)d_out;

    float *xl, *xr, *h1;
    cudaGetSymbolAddress((void**)&xl, g_xl);
    cudaGetSymbolAddress((void**)&xr, g_xr);
    cudaGetSymbolAddress((void**)&h1, g_h1);

    const int TB = 256;
    int gGemm = (N + 127) / 128;
    int gHist = (E + TB * 8 - 1) / (TB * 8);
    int gFat  = 2 * (gGemm > gHist ? gGemm : gHist);
    int nblk  = (N + NODES_PER_BLK - 1) / NODES_PER_BLK;
    int gNode = (N * 32 + TB - 1) / TB;

    // 1: gemm1 + degree histogram (interleaved by block parity)
    fat_gemm1_hist<<<gFat, TB>>>(x, W1l, W1r, xl, xr, N, dstp, E, gGemm, gHist);
    // 2: CSR offsets via decoupled lookback (restores g_deg)
    scan_lookback<<<nblk, TB>>>(N, nblk);
    // 3: CSR scatter (byte offsets; restores g_flag)
    scatter8<<<(E + TB * 8 - 1) / (TB * 8), TB>>>(srcp, dstp, E);
    // 4: layer-1 attention (profiled slot)
    gat_node<<<gNode, TB>>>(xl, xr, att1, b1, h1, N);
    // 5: layer-2 GEMM
    gemm_tiled<DD><<<gGemm, TB>>>(h1, W2l, W2r, xl, xr, N);
    // 6: layer-2 attention
    gat_node<<<gNode, TB>>>(xl, xr, att2, b2, out, N);
}

// round 10
// speedup vs baseline: 1.3671x; 1.3671x over previous
#include <cuda_runtime.h>
#include <math.h>

// Problem constants (fixed by setup_inputs)
#define NN 100000
#define EE 1600000
#define HH 4
#define CC 16
#define DD 64
#define FF 128
#define ET_MAX (EE + NN)
#define NODES_PER_BLK 1024
#define MAX_SCAN_BLKS 128

// ---------------- scratch (device globals; no runtime allocation) ----------------
// INVARIANTS at kernel_launch entry (zero-init at load; restored every call):
//   g_deg  all-zero  (scan_lookback re-zeroes after consuming)
//   g_flag all-zero  (scatter8 re-zeroes after scan completes)
// g_csr_src holds node indices; 16-entry zero pad allows clamp-free lookahead.
__device__ float g_xl[(size_t)NN * DD];
__device__ float g_xr[(size_t)NN * DD];
__device__ float g_h1[(size_t)NN * DD];
__device__ int   g_deg[NN];
__device__ int   g_off[NN + 1];
__device__ int   g_cur[NN];
__device__ unsigned g_flag[MAX_SCAN_BLKS];
__device__ int   g_csr_src[ET_MAX + 16];

// ---------------- helpers ----------------
__device__ __forceinline__ void ffma2(unsigned long long& acc,
                                      unsigned long long a, unsigned long long b) {
    asm("fma.rn.f32x2 %0, %1, %2, %0;" : "+l"(acc) : "l"(a), "l"(b));
}
__device__ __forceinline__ unsigned long long bcast2(float v) {
    unsigned long long r;
    asm("mov.b64 %0, {%1, %1};" : "=l"(r) : "r"(__float_as_uint(v)));
    return r;
}

// ================= GEMM body: 128 rows x (Wl||Wr 64+64 cols), 8x8 per thread =================
template<int K>
__device__ __forceinline__ void gemm_body(int blk,
                                          const float* __restrict__ X,
                                          const float* __restrict__ Wl,
                                          const float* __restrict__ Wr,
                                          float* __restrict__ xl,
                                          float* __restrict__ xr, int n,
                                          float (*As)[132], float (*Bs)[132]) {
    int tid = threadIdx.x;
    int rg = tid >> 4;
    int cg = tid & 15;
    int row0 = blk * 128;

    unsigned long long cl[8][2], cr[8][2];
#pragma unroll
    for (int i = 0; i < 8; i++) { cl[i][0] = cl[i][1] = cr[i][0] = cr[i][1] = 0ULL; }

    int lr  = tid >> 1;
    int lks = (tid & 1) * 8;
    int bk  = tid >> 4;
    int bc  = (tid & 15) * 8;

    for (int kc = 0; kc < K; kc += 16) {
        {
            int grow = row0 + lr;
            float4 v0 = make_float4(0.f, 0.f, 0.f, 0.f), v1 = v0;
            if (grow < n) {
                const float* g = X + (size_t)grow * K + kc + lks;
                v0 = *(const float4*)g;
                v1 = *(const float4*)(g + 4);
            }
            As[lks + 0][lr] = v0.x; As[lks + 1][lr] = v0.y;
            As[lks + 2][lr] = v0.z; As[lks + 3][lr] = v0.w;
            As[lks + 4][lr] = v1.x; As[lks + 5][lr] = v1.y;
            As[lks + 6][lr] = v1.z; As[lks + 7][lr] = v1.w;
        }
        {
            const float* wsrc = (bc < 64) ? (Wl + (size_t)(kc + bk) * DD + bc)
                                          : (Wr + (size_t)(kc + bk) * DD + (bc - 64));
            *(float4*)&Bs[bk][bc]     = *(const float4*)wsrc;
            *(float4*)&Bs[bk][bc + 4] = *(const float4*)(wsrc + 4);
        }
        __syncthreads();

#pragma unroll
        for (int k = 0; k < 16; k++) {
            float4 a01 = *(const float4*)&As[k][rg * 8];
            float4 a23 = *(const float4*)&As[k][rg * 8 + 4];
            ulonglong2 bl = *(const ulonglong2*)&Bs[k][cg * 4];
            ulonglong2 br = *(const ulonglong2*)&Bs[k][cg * 4 + 64];
            unsigned long long ab[8];
            ab[0] = bcast2(a01.x); ab[1] = bcast2(a01.y);
            ab[2] = bcast2(a01.z); ab[3] = bcast2(a01.w);
            ab[4] = bcast2(a23.x); ab[5] = bcast2(a23.y);
            ab[6] = bcast2(a23.z); ab[7] = bcast2(a23.w);
#pragma unroll
            for (int i = 0; i < 8; i++) {
                ffma2(cl[i][0], ab[i], bl.x); ffma2(cl[i][1], ab[i], bl.y);
                ffma2(cr[i][0], ab[i], br.x); ffma2(cr[i][1], ab[i], br.y);
            }
        }
        __syncthreads();
    }

#pragma unroll
    for (int i = 0; i < 8; i++) {
        int row = row0 + rg * 8 + i;
        if (row < n) {
            *(ulonglong2*)(xl + (size_t)row * DD + cg * 4) = make_ulonglong2(cl[i][0], cl[i][1]);
            *(ulonglong2*)(xr + (size_t)row * DD + cg * 4) = make_ulonglong2(cr[i][0], cr[i][1]);
        }
    }
}

// ---------------- hist body: 8 edges per thread ----------------
__device__ __forceinline__ void hist_body(int blk, const int* __restrict__ dst, int E) {
    int i = (blk * 256 + threadIdx.x) * 8;
    if (i + 7 < E) {
        int4 a = *(const int4*)(dst + i);
        int4 b = *(const int4*)(dst + i + 4);
        atomicAdd(&g_deg[a.x], 1); atomicAdd(&g_deg[a.y], 1);
        atomicAdd(&g_deg[a.z], 1); atomicAdd(&g_deg[a.w], 1);
        atomicAdd(&g_deg[b.x], 1); atomicAdd(&g_deg[b.y], 1);
        atomicAdd(&g_deg[b.z], 1); atomicAdd(&g_deg[b.w], 1);
    } else {
        for (int j = 0; j < 8; j++)
            if (i + j < E) atomicAdd(&g_deg[__ldg(dst + i + j)], 1);
    }
}

// ================= fat kernel 1: gemm1 (even blocks) + hist (odd blocks) =================
__global__ __launch_bounds__(256, 2)
void fat_gemm1_hist(const float* __restrict__ X,
                    const float* __restrict__ Wl,
                    const float* __restrict__ Wr,
                    float* __restrict__ xl, float* __restrict__ xr, int n,
                    const int* __restrict__ dst, int E, int gGemm, int gHist) {
    __shared__ float As[16][132];
    __shared__ float Bs[16][132];
    int bid = blockIdx.x;
    int g = bid >> 1;
    if ((bid & 1) == 0) {
        if (g < gGemm) gemm_body<FF>(g, X, Wl, Wr, xl, xr, n, As, Bs);
    } else {
        if (g < gHist) hist_body(g, dst, E);
    }
}

// ================= standalone GEMM (layer 2) =================
template<int K>
__global__ __launch_bounds__(256, 2)
void gemm_tiled(const float* __restrict__ X,
                const float* __restrict__ Wl,
                const float* __restrict__ Wr,
                float* __restrict__ xl, float* __restrict__ xr, int n) {
    __shared__ float As[16][132];
    __shared__ float Bs[16][132];
    gemm_body<K>(blockIdx.x, X, Wl, Wr, xl, xr, n, As, Bs);
}

// ================= decoupled-lookback scan (one kernel) =================
__global__ void scan_lookback(int n, int nblk) {
    __shared__ int sh[256];
    __shared__ int s_prefix;
    int t = threadIdx.x, b = blockIdx.x;
    int i0 = b * NODES_PER_BLK + t * 4;

    int d0 = 0, d1 = 0, d2 = 0, d3 = 0;
    if (i0 + 3 < n) {
        int4 d = *(const int4*)(g_deg + i0);
        d0 = d.x + 1; d1 = d.y + 1; d2 = d.z + 1; d3 = d.w + 1;
        *(int4*)(g_deg + i0) = make_int4(0, 0, 0, 0);
    } else {
        if (i0 + 0 < n) { d0 = g_deg[i0 + 0] + 1; g_deg[i0 + 0] = 0; }
        if (i0 + 1 < n) { d1 = g_deg[i0 + 1] + 1; g_deg[i0 + 1] = 0; }
        if (i0 + 2 < n) { d2 = g_deg[i0 + 2] + 1; g_deg[i0 + 2] = 0; }
        if (i0 + 3 < n) { d3 = g_deg[i0 + 3] + 1; g_deg[i0 + 3] = 0; }
    }
    int tsum = d0 + d1 + d2 + d3;
    sh[t] = tsum; __syncthreads();
    for (int d = 1; d < 256; d <<= 1) {
        int v = (t >= d) ? sh[t - d] : 0;
        __syncthreads();
        sh[t] += v;
        __syncthreads();
    }
    int T = sh[255];

    volatile unsigned* flag = g_flag;
    if (t == 0) {
        if (b == 0) {
            s_prefix = 0;
            flag[0] = (2u << 30) | (unsigned)T;
        } else {
            flag[b] = (1u << 30) | (unsigned)T;
            unsigned run = 0;
            int j = b - 1;
            while (true) {
                unsigned v = flag[j];
                unsigned st = v >> 30;
                if (st == 0) continue;
                run += v & 0x3FFFFFFFu;
                if (st == 2u) break;
                j--;
            }
            s_prefix = (int)run;
            flag[b] = (2u << 30) | (run + (unsigned)T);
        }
    }
    __syncthreads();
    int base = s_prefix + sh[t] - tsum;

    int dd[4] = {d0, d1, d2, d3};
    int o = base;
    for (int j = 0; j < 4; j++) {
        int i = i0 + j;
        if (i < n) {
            g_off[i] = o;
            g_csr_src[o] = i;          // self loop first
            g_cur[i] = o + 1;
        }
        o += dd[j];
    }
    if (b == nblk - 1 && t == 255) g_off[n] = s_prefix + T;
}

// ================= scatter (restores g_flag) =================
__global__ void scatter8(const int* __restrict__ src,
                         const int* __restrict__ dst, int E) {
    if (blockIdx.x == 0 && threadIdx.x < MAX_SCAN_BLKS)
        g_flag[threadIdx.x] = 0;
    int i = (blockIdx.x * blockDim.x + threadIdx.x) * 8;
    if (i + 7 < E) {
        int4 sa = *(const int4*)(src + i);
        int4 da = *(const int4*)(dst + i);
        int4 sb = *(const int4*)(src + i + 4);
        int4 db = *(const int4*)(dst + i + 4);
        int p0 = atomicAdd(&g_cur[da.x], 1);
        int p1 = atomicAdd(&g_cur[da.y], 1);
        int p2 = atomicAdd(&g_cur[da.z], 1);
        int p3 = atomicAdd(&g_cur[da.w], 1);
        int p4 = atomicAdd(&g_cur[db.x], 1);
        int p5 = atomicAdd(&g_cur[db.y], 1);
        int p6 = atomicAdd(&g_cur[db.z], 1);
        int p7 = atomicAdd(&g_cur[db.w], 1);
        g_csr_src[p0] = sa.x; g_csr_src[p1] = sa.y;
        g_csr_src[p2] = sa.z; g_csr_src[p3] = sa.w;
        g_csr_src[p4] = sb.x; g_csr_src[p5] = sb.y;
        g_csr_src[p6] = sb.z; g_csr_src[p7] = sb.w;
    } else {
        for (int j = 0; j < 8; j++)
            if (i + j < E) {
                int s = __ldg(src + i + j), d = __ldg(dst + i + j);
                g_csr_src[atomicAdd(&g_cur[d], 1)] = s;
            }
    }
}

// ================= fused GATv2 attention + aggregate + bias + ReLU =================
// R6 structure: warp per dst node; 16 lanes/edge (lane owns 4 dims), 2 edges per
// step, 2-deep pipeline. Changes vs R6:
//  - no index clamps (16-entry CSR pad; p=0 predication discards overreads)
//  - 3-op scoring per dim: t_lin += a*u; t_abs += a*|u| (|u| free FFMA modifier),
//    combined once per edge as t = 0.6*t_lin + 0.4*t_abs
__global__ void gat_node(const float* __restrict__ xl,
                         const float* __restrict__ xr,
                         const float* __restrict__ att,
                         const float* __restrict__ bias,
                         float* __restrict__ out, int n) {
    int w    = (blockIdx.x * blockDim.x + threadIdx.x) >> 5;
    int lane = threadIdx.x & 31;
    if (w >= n) return;
    int half = lane >> 4;
    int sub  = lane & 15;

    float4 xrv  = *(const float4*)(xr  + (size_t)w * DD + sub * 4);
    float4 attv = *(const float4*)(att + sub * 4);

    int beg = g_off[w], end = g_off[w + 1];
    int rem = end - beg;
    const int* ip = g_csr_src + beg;

    float s = 0.f, a0 = 0.f, a1 = 0.f, a2 = 0.f, a3 = 0.f;

    // pipeline prologue: rows for trip 0, indices for trip 1 (pad covers overread)
    int c0 = __ldg(ip + half);
    int c1 = __ldg(ip + 2 + half);
    float4 v0 = *(const float4*)(xl + (size_t)c0 * DD + sub * 4);
    float4 v1 = *(const float4*)(xl + (size_t)c1 * DD + sub * 4);
    int n0 = __ldg(ip + 4 + half);
    int n1 = __ldg(ip + 6 + half);

    for (int i = 0; i < rem; i += 4) {
        // prefetch: rows for trip i+4, indices for trip i+8
        float4 w0 = *(const float4*)(xl + (size_t)n0 * DD + sub * 4);
        float4 w1 = *(const float4*)(xl + (size_t)n1 * DD + sub * 4);
        int m0 = __ldg(ip + i + 8 + half);
        int m1 = __ldg(ip + i + 10 + half);

        float u, l0 = 0.f, b0f = 0.f, l1 = 0.f, b1f = 0.f;
        u = v0.x + xrv.x; l0 = fmaf(attv.x, u, l0); b0f = fmaf(attv.x, fabsf(u), b0f);
        u = v0.y + xrv.y; l0 = fmaf(attv.y, u, l0); b0f = fmaf(attv.y, fabsf(u), b0f);
        u = v0.z + xrv.z; l0 = fmaf(attv.z, u, l0); b0f = fmaf(attv.z, fabsf(u), b0f);
        u = v0.w + xrv.w; l0 = fmaf(attv.w, u, l0); b0f = fmaf(attv.w, fabsf(u), b0f);
        u = v1.x + xrv.x; l1 = fmaf(attv.x, u, l1); b1f = fmaf(attv.x, fabsf(u), b1f);
        u = v1.y + xrv.y; l1 = fmaf(attv.y, u, l1); b1f = fmaf(attv.y, fabsf(u), b1f);
        u = v1.z + xrv.z; l1 = fmaf(attv.z, u, l1); b1f = fmaf(attv.z, fabsf(u), b1f);
        u = v1.w + xrv.w; l1 = fmaf(attv.w, u, l1); b1f = fmaf(attv.w, fabsf(u), b1f);
        float t0 = fmaf(0.6f, l0, 0.4f * b0f);
        float t1 = fmaf(0.6f, l1, 0.4f * b1f);

        t0 += __shfl_xor_sync(0xffffffffu, t0, 1);
        t1 += __shfl_xor_sync(0xffffffffu, t1, 1);
        t0 += __shfl_xor_sync(0xffffffffu, t0, 2);
        t1 += __shfl_xor_sync(0xffffffffu, t1, 2);

        float p0 = (i + half     < rem) ? __expf(t0) : 0.f;
        float p1 = (i + 2 + half < rem) ? __expf(t1) : 0.f;
        s += p0 + p1;
        a0 = fmaf(p0, v0.x, fmaf(p1, v1.x, a0));
        a1 = fmaf(p0, v0.y, fmaf(p1, v1.y, a1));
        a2 = fmaf(p0, v0.z, fmaf(p1, v1.z, a2));
        a3 = fmaf(p0, v0.w, fmaf(p1, v1.w, a3));

        v0 = w0; v1 = w1; n0 = m0; n1 = m1;
    }

    // combine the two half-warps (disjoint edge sets, same dims)
    s  += __shfl_xor_sync(0xffffffffu, s,  16);
    a0 += __shfl_xor_sync(0xffffffffu, a0, 16);
    a1 += __shfl_xor_sync(0xffffffffu, a1, 16);
    a2 += __shfl_xor_sync(0xffffffffu, a2, 16);
    a3 += __shfl_xor_sync(0xffffffffu, a3, 16);

    if (half == 0) {
        float4 bv = *(const float4*)(bias + sub * 4);
        float inv = __fdividef(1.f, s);
        float4 o;
        o.x = fmaxf(fmaf(a0, inv, bv.x), 0.f);
        o.y = fmaxf(fmaf(a1, inv, bv.y), 0.f);
        o.z = fmaxf(fmaf(a2, inv, bv.z), 0.f);
        o.w = fmaxf(fmaf(a3, inv, bv.w), 0.f);
        *(float4*)(out + (size_t)w * DD + sub * 4) = o;
    }
}

// ---------------- launch ----------------
extern "C" void kernel_launch(void* const* d_in, const int* in_sizes, int n_in,
                              void* d_out, int out_size) {
    const float* x    = (const float*)d_in[0];
    const int*   edge = (const int*)  d_in[1];
    const float* W1l  = (const float*)d_in[2];
    const float* W1r  = (const float*)d_in[3];
    const float* att1 = (const float*)d_in[4];
    const float* b1   = (const float*)d_in[5];
    const float* W2l  = (const float*)d_in[6];
    const float* W2r  = (const float*)d_in[7];
    const float* att2 = (const float*)d_in[8];
    const float* b2   = (const float*)d_in[9];

    int E = in_sizes[1] / 2;
    int N = in_sizes[0] / FF;
    const int* srcp = edge;
    const int* dstp = edge + E;
    float* out = (float*)d_out;

    float *xl, *xr, *h1;
    cudaGetSymbolAddress((void**)&xl, g_xl);
    cudaGetSymbolAddress((void**)&xr, g_xr);
    cudaGetSymbolAddress((void**)&h1, g_h1);

    const int TB = 256;
    int gGemm = (N + 127) / 128;
    int gHist = (E + TB * 8 - 1) / (TB * 8);
    int gFat  = 2 * (gGemm > gHist ? gGemm : gHist);
    int nblk  = (N + NODES_PER_BLK - 1) / NODES_PER_BLK;
    int gNode = (N * 32 + TB - 1) / TB;

    // 1: gemm1 + degree histogram (interleaved by block parity)
    fat_gemm1_hist<<<gFat, TB>>>(x, W1l, W1r, xl, xr, N, dstp, E, gGemm, gHist);
    // 2: CSR offsets via decoupled lookback (restores g_deg)
    scan_lookback<<<nblk, TB>>>(N, nblk);
    // 3: CSR scatter (restores g_flag)
    scatter8<<<(E + TB * 8 - 1) / (TB * 8), TB>>>(srcp, dstp, E);
    // 4: layer-1 attention (profiled slot)
    gat_node<<<gNode, TB>>>(xl, xr, att1, b1, h1, N);
    // 5: layer-2 GEMM
    gemm_tiled<DD><<<gGemm, TB>>>(h1, W2l, W2r, xl, xr, N);
    // 6: layer-2 attention
    gat_node<<<gNode, TB>>>(xl, xr, att2, b2, out, N);
}